// round 5
// baseline (speedup 1.0000x reference)
#include <cuda_runtime.h>

#define BB 32
#define SS 128
#define KN 12
#define KC 10
#define KT 22
#define DD 200
#define D4 50
#define CC 45
#define CP 48
#define CP4 12
#define FF 1000
#define NTOK 4096

#define TPB 384
#define FTOK 6
#define FEATB ((NTOK + FTOK - 1) / FTOK)    // 683
#define GT 32
#define NTILES (NTOK / GT)                  // 128
#define GEMMB (NTILES * 5)                  // 640
#define REDB NTILES                         // 128
#define APAD 51                             // shA pitch in float4 (204 floats)

__device__ float g_feat[NTOK * DD];
__device__ float g_part[5 * NTOK * CP];
__device__ int   g_tokflag[NTOK];
__device__ int   g_tilecnt[NTILES];

__device__ __forceinline__ int ld_acquire(const int* p) {
    int v;
    asm volatile("ld.acquire.gpu.b32 %0, [%1];" : "=r"(v) : "l"(p) : "memory");
    return v;
}

// ---------------------------------------------------------------------------
// Reset flags/counters (graph replays reuse device globals -> must re-zero)
// ---------------------------------------------------------------------------
__global__ void reset_kernel() {
    int i = blockIdx.x * blockDim.x + threadIdx.x;
    if (i < NTOK) g_tokflag[i] = 0;
    if (i < NTILES) g_tilecnt[i] = 0;
}

// ---------------------------------------------------------------------------
// Fused kernel: [feat blocks | gemm blocks | reduce blocks], flag dataflow.
// Dispatch is in-bid-order: feat never waits -> no deadlock.
// ---------------------------------------------------------------------------
__global__ void __launch_bounds__(TPB)
fused_kernel(const int* __restrict__ ngram_ids,
             const int* __restrict__ ngram_mask,
             const int* __restrict__ ctx_ids,
             const int* __restrict__ ctx_mask,
             const float* __restrict__ embed,
             const float* __restrict__ W,
             const float* __restrict__ bias,
             float* __restrict__ out) {
    const int bid = blockIdx.x;

    // ======================= FEAT: masked gather + mean ====================
    if (bid < FEATB) {
        const int g    = threadIdx.x >> 6;       // 0..5 token group
        const int lane = threadIdx.x & 63;
        const int tok  = bid * FTOK + g;
        const bool valid = (tok < NTOK);

        __shared__ int s_act[FTOK][24];
        __shared__ int s_cnt[FTOK];

        if (valid && lane < 32) {                // warp 0 of group: compact ids
            int m = 0, id = 0;
            if (lane < KN) {
                id = ngram_ids[tok * KN + lane];
                m  = ngram_mask[tok * KN + lane];
            } else if (lane < KT) {
                id = ctx_ids[tok * KC + lane - KN];
                m  = ctx_mask[tok * KC + lane - KN];
            }
            unsigned bal = __ballot_sync(0xffffffffu, m != 0);
            if (m) s_act[g][__popc(bal & ((1u << lane) - 1u))] = id;
            if (lane == 0) s_cnt[g] = __popc(bal);
        }
        __syncthreads();

        if (valid && lane < D4) {
            const int n = s_cnt[g];
            const int* act = s_act[g];
            const float4* e4 = (const float4*)embed;
            float ax = 0.f, ay = 0.f, az = 0.f, aw = 0.f;
            int j = 0;
            for (; j + 8 <= n; j += 8) {         // 8 LDG.128 in flight
                float4 v0 = e4[(long long)act[j + 0] * D4 + lane];
                float4 v1 = e4[(long long)act[j + 1] * D4 + lane];
                float4 v2 = e4[(long long)act[j + 2] * D4 + lane];
                float4 v3 = e4[(long long)act[j + 3] * D4 + lane];
                float4 v4 = e4[(long long)act[j + 4] * D4 + lane];
                float4 v5 = e4[(long long)act[j + 5] * D4 + lane];
                float4 v6 = e4[(long long)act[j + 6] * D4 + lane];
                float4 v7 = e4[(long long)act[j + 7] * D4 + lane];
                ax += ((v0.x + v1.x) + (v2.x + v3.x)) + ((v4.x + v5.x) + (v6.x + v7.x));
                ay += ((v0.y + v1.y) + (v2.y + v3.y)) + ((v4.y + v5.y) + (v6.y + v7.y));
                az += ((v0.z + v1.z) + (v2.z + v3.z)) + ((v4.z + v5.z) + (v6.z + v7.z));
                aw += ((v0.w + v1.w) + (v2.w + v3.w)) + ((v4.w + v5.w) + (v6.w + v7.w));
            }
            for (; j + 4 <= n; j += 4) {
                float4 v0 = e4[(long long)act[j + 0] * D4 + lane];
                float4 v1 = e4[(long long)act[j + 1] * D4 + lane];
                float4 v2 = e4[(long long)act[j + 2] * D4 + lane];
                float4 v3 = e4[(long long)act[j + 3] * D4 + lane];
                ax += (v0.x + v1.x) + (v2.x + v3.x);
                ay += (v0.y + v1.y) + (v2.y + v3.y);
                az += (v0.z + v1.z) + (v2.z + v3.z);
                aw += (v0.w + v1.w) + (v2.w + v3.w);
            }
            for (; j < n; j++) {
                float4 v = e4[(long long)act[j] * D4 + lane];
                ax += v.x; ay += v.y; az += v.z; aw += v.w;
            }
            float inv = 1.0f / (float)(n > 0 ? n : 1);
            float4 r; r.x = ax * inv; r.y = ay * inv; r.z = az * inv; r.w = aw * inv;
            ((float4*)g_feat)[tok * D4 + lane] = r;
        }

        __syncthreads();                          // all token writes done
        __threadfence();
        if (threadIdx.x < FTOK) {
            int t = bid * FTOK + threadIdx.x;
            if (t < NTOK)
                asm volatile("st.release.gpu.b32 [%0], %1;"
                             :: "l"(&g_tokflag[t]), "r"(1) : "memory");
        }
        return;
    }

    // ======================= GEMM: per-window partial ======================
    if (bid < FEATB + GEMMB) {
        __shared__ float4 shA[GT * APAD];        // 26112 B
        __shared__ float4 shB[100 * CP4];        // 19200 B
        float* shBf = (float*)shB;

        const int q = bid - FEATB;
        const int tile = q / 5;
        const int w = q - tile * 5;
        const int tokBase = tile * GT;
        const int b  = tokBase / SS;
        const int s0 = tokBase % SS;

        const int tid = threadIdx.x;

        // wait for the <=32 feat tokens this block reads
        if (tid < GT) {
            int s = s0 + w - 2 + tid;
            if (s >= 0 && s < SS) {
                const int* f = &g_tokflag[b * SS + s];
                while (ld_acquire(f) == 0) __nanosleep(32);
            }
        }
        __syncthreads();

        const int lane = tid & 31;
        const int upper = tid >> 5;
        const int tg = (lane & 15) + 16 * (upper & 1);
        const int cg = (upper >> 1) * 2 + (lane >> 4);

        // stage A: feat rows s0+w-2 .. s0+w+29 (zero halo)
        const float4* gf4 = (const float4*)g_feat;
        for (int i = tid; i < GT * D4; i += TPB) {
            int r  = i / D4;
            int dv = i - r * D4;
            int s  = s0 + w - 2 + r;
            float4 v = make_float4(0.f, 0.f, 0.f, 0.f);
            if (s >= 0 && s < SS) v = gf4[(b * SS + s) * D4 + dv];
            shA[r * APAD + dv] = v;
        }

        float acc0 = 0.f, acc1 = 0.f, acc2 = 0.f, acc3 = 0.f;

        #pragma unroll
        for (int h = 0; h < 2; h++) {
            __syncthreads();
            // stage B from W directly (transposed on the fly):
            // shBf[kk*48 + c] = W[c, w*200 + h*100 + kk]; coalesced along kk
            for (int i = tid; i < 100 * CP; i += TPB) {
                int c  = i / 100;
                int kk = i - c * 100;
                shBf[kk * CP + c] =
                    (c < CC) ? W[c * FF + w * DD + h * 100 + kk] : 0.0f;
            }
            __syncthreads();

            const float4* aRow = &shA[tg * APAD + h * 25];
            #pragma unroll
            for (int dq = 0; dq < 25; dq++) {
                float4 a  = aRow[dq];
                float4 b0 = shB[(dq * 4 + 0) * CP4 + cg];
                float4 b1 = shB[(dq * 4 + 1) * CP4 + cg];
                float4 b2 = shB[(dq * 4 + 2) * CP4 + cg];
                float4 b3 = shB[(dq * 4 + 3) * CP4 + cg];
                acc0 = fmaf(a.x, b0.x, acc0); acc1 = fmaf(a.x, b0.y, acc1);
                acc2 = fmaf(a.x, b0.z, acc2); acc3 = fmaf(a.x, b0.w, acc3);
                acc0 = fmaf(a.y, b1.x, acc0); acc1 = fmaf(a.y, b1.y, acc1);
                acc2 = fmaf(a.y, b1.z, acc2); acc3 = fmaf(a.y, b1.w, acc3);
                acc0 = fmaf(a.z, b2.x, acc0); acc1 = fmaf(a.z, b2.y, acc1);
                acc2 = fmaf(a.z, b2.z, acc2); acc3 = fmaf(a.z, b2.w, acc3);
                acc0 = fmaf(a.w, b3.x, acc0); acc1 = fmaf(a.w, b3.y, acc1);
                acc2 = fmaf(a.w, b3.z, acc2); acc3 = fmaf(a.w, b3.w, acc3);
            }
        }

        float4 v; v.x = acc0; v.y = acc1; v.z = acc2; v.w = acc3;
        ((float4*)g_part)[((long long)w * NTOK + tokBase + tg) * CP4 + cg] = v;

        __syncthreads();
        if (tid == 0) {
            __threadfence();
            atomicAdd(&g_tilecnt[tile], 1);
        }
        return;
    }

    // ======================= REDUCE: 5 partials + bias =====================
    {
        const int tile = bid - FEATB - GEMMB;
        if (threadIdx.x == 0) {
            while (ld_acquire(&g_tilecnt[tile]) < 5) __nanosleep(32);
        }
        __syncthreads();

        const int t  = threadIdx.x / CP4;        // 0..31 token in tile
        const int cg = threadIdx.x % CP4;        // 0..11
        const int tok = tile * GT + t;

        const float4* p4 = (const float4*)g_part;
        float4 s = make_float4(0.f, 0.f, 0.f, 0.f);
        #pragma unroll
        for (int w = 0; w < 5; w++) {
            float4 v = p4[((long long)w * NTOK + tok) * CP4 + cg];
            s.x += v.x; s.y += v.y; s.z += v.z; s.w += v.w;
        }
        int c0 = cg * 4;
        float* o = out + (long long)tok * CC;
        if (c0 + 0 < CC) o[c0 + 0] = s.x + bias[c0 + 0];
        if (c0 + 1 < CC) o[c0 + 1] = s.y + bias[c0 + 1];
        if (c0 + 2 < CC) o[c0 + 2] = s.z + bias[c0 + 2];
        if (c0 + 3 < CC) o[c0 + 3] = s.w + bias[c0 + 3];
    }
}

// ---------------------------------------------------------------------------
extern "C" void kernel_launch(void* const* d_in, const int* in_sizes, int n_in,
                              void* d_out, int out_size) {
    const int*   ngram_ids  = (const int*)d_in[0];
    const int*   ngram_mask = (const int*)d_in[1];
    const int*   ctx_ids    = (const int*)d_in[2];
    const int*   ctx_mask   = (const int*)d_in[3];
    const float* embed      = (const float*)d_in[4];
    const float* W          = (const float*)d_in[5];
    const float* bias       = (const float*)d_in[6];
    float* out = (float*)d_out;

    reset_kernel<<<(NTOK + 1023) / 1024, 1024>>>();
    fused_kernel<<<FEATB + GEMMB + REDB, TPB>>>(
        ngram_ids, ngram_mask, ctx_ids, ctx_mask, embed, W, bias, out);
}